// round 11
// baseline (speedup 1.0000x reference)
#include <cuda_runtime.h>
#include <cuda_bf16.h>
#include <cstdint>

// Device-global scratch (no allocations). Zero-init; last block resets.
__device__ double        g_acc       = 0.0;
__device__ unsigned int  g_acc_count = 0;

#define LOG2E 1.44269504088896340736f
#define LN2   0.69314718055994530942f

// chunk = 32 groups (128 rows): 1536 B logits + 512 B targets = 2048 B/stage
#define CHUNK_LB   1536
#define CHUNK_TB   512
#define STAGE_B    2048
#define WARP_SMEM  (2 * STAGE_B)      // double buffer per warp
#define NWARPS     8

__device__ __forceinline__ float rcp_approx(float x) {
    float r; asm("rcp.approx.f32 %0, %1;" : "=f"(r) : "f"(x)); return r;
}
__device__ __forceinline__ float ex2_approx(float x) {
    float r; asm("ex2.approx.f32 %0, %1;" : "=f"(r) : "f"(x)); return r;
}
__device__ __forceinline__ float lg2_approx(float x) {
    float r; asm("lg2.approx.f32 %0, %1;" : "=f"(r) : "f"(x)); return r;
}
__device__ __forceinline__ uint32_t smem_u32(const void* p) {
    uint32_t a;
    asm("{ .reg .u64 t; cvta.to.shared.u64 t, %1; cvt.u32.u64 %0, t; }"
        : "=r"(a) : "l"(p));
    return a;
}
__device__ __forceinline__ void cp16(uint32_t sdst, const void* gsrc) {
    asm volatile("cp.async.cg.shared.global [%0], [%1], 16;"
                 :: "r"(sdst), "l"(gsrc) : "memory");
}
// Issue one chunk (this lane's 48B logits + 16B targets) into stage `sbase`.
__device__ __forceinline__ void issue_chunk(uint32_t sbase, int lane48, int lane16,
                                            const char* lsrc, const char* tsrc)
{
    cp16(sbase + lane48 +  0, lsrc + lane48 +  0);
    cp16(sbase + lane48 + 16, lsrc + lane48 + 16);
    cp16(sbase + lane48 + 32, lsrc + lane48 + 32);
    cp16(sbase + CHUNK_LB + lane16, tsrc + lane16);
    asm volatile("cp.async.commit_group;" ::: "memory");
}

// tbl[p*3+t] = { 1.5*P[p][t],  0.1*(p!=t),  class_w[t]*ln2,  0 }
__device__ __forceinline__ void row_loss(float l0, float l1, float l2, int t,
                                         const float4* __restrict__ tbl,
                                         float& acc, float& accP)
{
    // exact first-occurrence argmax (strict > matches jnp.argmax)
    const bool  pa  = (l1 > l0);
    const float m01 = fmaxf(l0, l1);
    const bool  pb  = (l2 > m01);
    const float m   = fmaxf(m01, l2);

    const int p3  = pb ? 6 : (pa ? 3 : 0);
    const float4 e = tbl[p3 + t];

    const float nmK = -m * LOG2E;
    const float s0 = fmaf(l0, LOG2E, nmK);
    const float s1 = fmaf(l1, LOG2E, nmK);
    const float s2 = fmaf(l2, LOG2E, nmK);

    const float e0 = ex2_approx(s0);
    const float e1 = ex2_approx(s1);
    const float e2 = ex2_approx(s2);
    const float S    = e0 + e1 + e2;
    const float rcpS = rcp_approx(S);          // == max prob (exp at argmax is 1)
    const float lg2S = lg2_approx(S);

    const float st = (t == 0) ? s0 : ((t == 1) ? s1 : s2);
    const float et = (t == 0) ? e0 : ((t == 1) ? e1 : e2);

    const float omp = fmaf(-et, rcpS, 1.0f);   // 1 - prob[target]
    const float ce2 = lg2S - st;               // ce / ln2

    acc  = fmaf((e.z * omp) * omp, ce2, acc);  // focal
    acc  = fmaf(e.y, rcpS, acc);               // 0.1*(p!=t)*max_prob
    accP += e.x;                               // 1.5*penalty
}

__device__ __forceinline__ void process_group(const char* sl, int lane,
                                              const float4* __restrict__ tbl,
                                              float& acc0, float& acc1, float& accP)
{
    const float4* lp = reinterpret_cast<const float4*>(sl + lane * 48);
    const float4 a0 = lp[0];
    const float4 a1 = lp[1];
    const float4 a2 = lp[2];
    const int4   t4 = *reinterpret_cast<const int4*>(sl + CHUNK_LB + lane * 16);

    row_loss(a0.x, a0.y, a0.z, t4.x, tbl, acc0, accP);
    row_loss(a0.w, a1.x, a1.y, t4.y, tbl, acc1, accP);
    row_loss(a1.z, a1.w, a2.x, t4.z, tbl, acc0, accP);
    row_loss(a2.y, a2.z, a2.w, t4.w, tbl, acc1, accP);
}

__global__ void __launch_bounds__(256, 5)
trading_loss_kernel(const float* __restrict__ logits,
                    const int*   __restrict__ targets,
                    const float* __restrict__ class_w,
                    float*       __restrict__ out,
                    int nchunks, int ngroups, float inv_n, int nblocks)
{
    __shared__ __align__(16) char buf[NWARPS * WARP_SMEM];   // 32 KB
    __shared__ float4 tbl[9];
    __shared__ float  warp_sums[NWARPS];
    __shared__ bool   is_last;

    const int tid  = threadIdx.x;
    const int lane = tid & 31;
    const int wid  = tid >> 5;

    if (tid < 9) {
        const int p = tid / 3;
        const int t = tid - p * 3;
        int d = p - t; d = (d < 0) ? -d : d;
        const float pen15 = 0.75f * (float)d + ((d == 2) ? 0.75f : 0.0f);
        const float confw = (d != 0) ? 0.1f : 0.0f;
        tbl[tid] = make_float4(pen15, confw, class_w[t] * LN2, 0.0f);
    }
    __syncthreads();

    float acc0 = 0.0f, acc1 = 0.0f, accP = 0.0f;

    const int wg = blockIdx.x * NWARPS + wid;      // global warp id
    const int tw = nblocks * NWARPS;               // total warps
    const int lane48 = lane * 48;
    const int lane16 = lane * 16;

    const uint32_t sb0 = smem_u32(buf) + (uint32_t)wid * WARP_SMEM;
    const uint32_t sb1 = sb0 + STAGE_B;
    const char* csl0 = buf + wid * WARP_SMEM;
    const char* csl1 = csl0 + STAGE_B;

    // chunk stream for this warp: c = wg, wg+tw, wg+2tw, ...
    int c = wg;
    if (c < nchunks) {
        issue_chunk(sb0, lane48, lane16,
                    (const char*)logits  + (size_t)c * CHUNK_LB,
                    (const char*)targets + (size_t)c * CHUNK_TB);

        int stage = 0;
        for (; c < nchunks; c += tw) {
            const int cn = c + tw;
            if (cn < nchunks) {
                issue_chunk(stage ? sb0 : sb1, lane48, lane16,
                            (const char*)logits  + (size_t)cn * CHUNK_LB,
                            (const char*)targets + (size_t)cn * CHUNK_TB);
                asm volatile("cp.async.wait_group 1;" ::: "memory");
            } else {
                asm volatile("cp.async.wait_group 0;" ::: "memory");
            }
            __syncwarp();

            process_group(stage ? csl1 : csl0, lane, tbl, acc0, acc1, accP);
            stage ^= 1;
        }
    }

    // remainder groups (ngroups % 32) via direct LDG — zero for bench shape
    const int rem_base = nchunks * 32;
    for (int g = rem_base + wg * 32 + lane; g < ngroups; g += tw * 32) {
        const float4* lp = reinterpret_cast<const float4*>(logits) + (size_t)g * 3;
        const float4 a0 = __ldg(lp + 0);
        const float4 a1 = __ldg(lp + 1);
        const float4 a2 = __ldg(lp + 2);
        const int4   t4 = __ldg(reinterpret_cast<const int4*>(targets) + g);
        row_loss(a0.x, a0.y, a0.z, t4.x, tbl, acc0, accP);
        row_loss(a0.w, a1.x, a1.y, t4.y, tbl, acc1, accP);
        row_loss(a1.z, a1.w, a2.x, t4.z, tbl, acc0, accP);
        row_loss(a2.y, a2.z, a2.w, t4.w, tbl, acc1, accP);
    }

    float acc = (acc0 + acc1) + accP;

    // ---- block reduction ----
    #pragma unroll
    for (int off = 16; off > 0; off >>= 1)
        acc += __shfl_xor_sync(0xFFFFFFFFu, acc, off);

    if (lane == 0) warp_sums[wid] = acc;
    __syncthreads();

    if (wid == 0) {
        float v = (lane < NWARPS) ? warp_sums[lane] : 0.0f;
        #pragma unroll
        for (int off = 4; off > 0; off >>= 1)
            v += __shfl_xor_sync(0xFFFFFFFFu, v, off);
        if (lane == 0) {
            atomicAdd(&g_acc, (double)v);
            __threadfence();
            unsigned int ticket = atomicAdd(&g_acc_count, 1u);
            is_last = (ticket == (unsigned int)nblocks - 1u);
        }
    }
    __syncthreads();

    if (is_last && tid == 0) {
        double total = g_acc;
        out[0] = (float)(total * (double)inv_n);
        g_acc = 0.0;
        g_acc_count = 0u;
    }
}

extern "C" void kernel_launch(void* const* d_in, const int* in_sizes, int n_in,
                              void* d_out, int out_size)
{
    const float* logits  = (const float*)d_in[0];
    const int*   targets = (const int*)d_in[1];
    const float* class_w = (const float*)d_in[2];
    float*       out     = (float*)d_out;

    const int batch   = in_sizes[1];       // targets element count = B
    const int ngroups = batch / 4;         // 4 rows per float4-group
    const int nchunks = ngroups / 32;      // 32 groups per warp-chunk

    int blocks = 152 * 5;                  // single wave at 5 blocks/SM
    int maxc   = (nchunks + NWARPS - 1) / NWARPS;
    if (blocks > maxc && maxc > 0) blocks = maxc;
    if (blocks < 1) blocks = 1;

    trading_loss_kernel<<<blocks, 256>>>(logits, targets, class_w, out,
                                         nchunks, ngroups,
                                         1.0f / (float)batch, blocks);
}

// round 12
// speedup vs baseline: 1.1568x; 1.1568x over previous
#include <cuda_runtime.h>
#include <cuda_bf16.h>
#include <cstdint>

// Device-global scratch (no allocations). Zero-init; last block resets.
__device__ double        g_acc       = 0.0;
__device__ unsigned int  g_acc_count = 0;

#define LOG2E 1.44269504088896340736f
#define LN2   0.69314718055994530942f

__device__ __forceinline__ float rcp_approx(float x) {
    float r; asm("rcp.approx.f32 %0, %1;" : "=f"(r) : "f"(x)); return r;
}
__device__ __forceinline__ float ex2_approx(float x) {
    float r; asm("ex2.approx.f32 %0, %1;" : "=f"(r) : "f"(x)); return r;
}
__device__ __forceinline__ float lg2_approx(float x) {
    float r; asm("lg2.approx.f32 %0, %1;" : "=f"(r) : "f"(x)); return r;
}

// tbl[p*3+t] = { 1.5*P[p][t],  0.1*(p!=t),  class_w[t]*ln2,  0 }
__device__ __forceinline__ void row_loss(float l0, float l1, float l2, int t,
                                         const float4* __restrict__ tbl,
                                         float& acc, float& accP)
{
    // exact first-occurrence argmax (strict > matches jnp.argmax)
    const bool  pa  = (l1 > l0);
    const float m01 = fmaxf(l0, l1);
    const bool  pb  = (l2 > m01);
    const float m   = fmaxf(m01, l2);

    const int p3  = pb ? 6 : (pa ? 3 : 0);     // p * 3
    const float4 e = tbl[p3 + t];              // {pen15, confw, aln2, -}

    // log2-domain shifted deltas; max lane is exactly 0 -> exp = 1
    const float nmK = -m * LOG2E;
    const float s0 = fmaf(l0, LOG2E, nmK);
    const float s1 = fmaf(l1, LOG2E, nmK);
    const float s2 = fmaf(l2, LOG2E, nmK);

    const float e0 = ex2_approx(s0);
    const float e1 = ex2_approx(s1);
    const float e2 = ex2_approx(s2);
    const float S    = e0 + e1 + e2;
    const float rcpS = rcp_approx(S);          // == max prob (exp at argmax is 1)
    const float lg2S = lg2_approx(S);

    const float st = (t == 0) ? s0 : ((t == 1) ? s1 : s2);
    const float et = (t == 0) ? e0 : ((t == 1) ? e1 : e2);

    const float omp = fmaf(-et, rcpS, 1.0f);   // 1 - prob[target]
    const float ce2 = lg2S - st;               // ce / ln2

    acc  = fmaf((e.z * omp) * omp, ce2, acc);  // focal
    acc  = fmaf(e.y, rcpS, acc);               // 0.1*(p!=t)*max_prob
    accP += e.x;                               // 1.5*penalty
}

__global__ void __launch_bounds__(256, 4)
trading_loss_kernel(const float* __restrict__ logits,
                    const int*   __restrict__ targets,
                    const float* __restrict__ class_w,
                    float*       __restrict__ out,
                    int ngroups, float inv_n, int nblocks)
{
    __shared__ float4 tbl[9];
    __shared__ float  warp_sums[8];
    __shared__ bool   is_last;

    if (threadIdx.x < 9) {
        const int p = threadIdx.x / 3;
        const int t = threadIdx.x - p * 3;
        int d = p - t; d = (d < 0) ? -d : d;
        const float pen15 = 0.75f * (float)d + ((d == 2) ? 0.75f : 0.0f);
        const float confw = (d != 0) ? 0.1f : 0.0f;
        tbl[threadIdx.x] = make_float4(pen15, confw, class_w[t] * LN2, 0.0f);
    }
    __syncthreads();

    float acc0 = 0.0f, acc1 = 0.0f, accP = 0.0f;

    const int tid    = blockIdx.x * blockDim.x + threadIdx.x;
    const int stride = gridDim.x * blockDim.x;

    const float4* lbase = reinterpret_cast<const float4*>(logits);
    const int4*   tbase = reinterpret_cast<const int4*>(targets);

    // Two independent groups per iteration; all 8 wide loads are issued
    // back-to-back with INDEPENDENT addressing (no carried pointer chain).
    int g = tid;
    for (; g + stride < ngroups; g += 2 * stride) {
        const int g2 = g + stride;
        const float4 a0 = __ldg(lbase + (size_t)g  * 3 + 0);
        const float4 a1 = __ldg(lbase + (size_t)g  * 3 + 1);
        const float4 a2 = __ldg(lbase + (size_t)g  * 3 + 2);
        const float4 b0 = __ldg(lbase + (size_t)g2 * 3 + 0);
        const float4 b1 = __ldg(lbase + (size_t)g2 * 3 + 1);
        const float4 b2 = __ldg(lbase + (size_t)g2 * 3 + 2);
        const int4   ta = __ldg(tbase + g);
        const int4   tb = __ldg(tbase + g2);

        row_loss(a0.x, a0.y, a0.z, ta.x, tbl, acc0, accP);
        row_loss(a0.w, a1.x, a1.y, ta.y, tbl, acc1, accP);
        row_loss(a1.z, a1.w, a2.x, ta.z, tbl, acc0, accP);
        row_loss(a2.y, a2.z, a2.w, ta.w, tbl, acc1, accP);
        row_loss(b0.x, b0.y, b0.z, tb.x, tbl, acc0, accP);
        row_loss(b0.w, b1.x, b1.y, tb.y, tbl, acc1, accP);
        row_loss(b1.z, b1.w, b2.x, tb.z, tbl, acc0, accP);
        row_loss(b2.y, b2.z, b2.w, tb.w, tbl, acc1, accP);
    }
    // tail: at most one remaining group
    if (g < ngroups) {
        const float4 a0 = __ldg(lbase + (size_t)g * 3 + 0);
        const float4 a1 = __ldg(lbase + (size_t)g * 3 + 1);
        const float4 a2 = __ldg(lbase + (size_t)g * 3 + 2);
        const int4   ta = __ldg(tbase + g);
        row_loss(a0.x, a0.y, a0.z, ta.x, tbl, acc0, accP);
        row_loss(a0.w, a1.x, a1.y, ta.y, tbl, acc1, accP);
        row_loss(a1.z, a1.w, a2.x, ta.z, tbl, acc0, accP);
        row_loss(a2.y, a2.z, a2.w, ta.w, tbl, acc1, accP);
    }

    float acc = (acc0 + acc1) + accP;

    // ---- block reduction ----
    #pragma unroll
    for (int off = 16; off > 0; off >>= 1)
        acc += __shfl_xor_sync(0xFFFFFFFFu, acc, off);

    const int lane = threadIdx.x & 31;
    const int wid  = threadIdx.x >> 5;
    if (lane == 0) warp_sums[wid] = acc;
    __syncthreads();

    if (wid == 0) {
        float v = (lane < (blockDim.x >> 5)) ? warp_sums[lane] : 0.0f;
        #pragma unroll
        for (int off = 4; off > 0; off >>= 1)
            v += __shfl_xor_sync(0xFFFFFFFFu, v, off);
        if (lane == 0) {
            atomicAdd(&g_acc, (double)v);
            __threadfence();
            unsigned int ticket = atomicAdd(&g_acc_count, 1u);
            is_last = (ticket == (unsigned int)nblocks - 1u);
        }
    }
    __syncthreads();

    if (is_last && threadIdx.x == 0) {
        double total = g_acc;
        out[0] = (float)(total * (double)inv_n);
        g_acc = 0.0;
        g_acc_count = 0u;
    }
}

extern "C" void kernel_launch(void* const* d_in, const int* in_sizes, int n_in,
                              void* d_out, int out_size)
{
    const float* logits  = (const float*)d_in[0];
    const int*   targets = (const int*)d_in[1];
    const float* class_w = (const float*)d_in[2];
    float*       out     = (float*)d_out;

    const int batch   = in_sizes[1];       // targets element count = B
    const int ngroups = batch / 4;         // 4 rows per float4-group

    const int threads = 256;
    int blocks = 152 * 4;                  // single wave at 4 blocks/SM (GB300)
    int maxb   = (ngroups + threads - 1) / threads;
    if (blocks > maxb) blocks = maxb;
    if (blocks < 1) blocks = 1;

    trading_loss_kernel<<<blocks, threads>>>(logits, targets, class_w, out,
                                             ngroups, 1.0f / (float)batch, blocks);
}

// round 13
// speedup vs baseline: 1.1672x; 1.0090x over previous
#include <cuda_runtime.h>
#include <cuda_bf16.h>
#include <cstdint>

// Device-global scratch (no allocations). Zero-init; last block resets.
__device__ double        g_acc       = 0.0;
__device__ unsigned int  g_acc_count = 0;

#define LOG2E 1.44269504088896340736f
#define LN2   0.69314718055994530942f

__device__ __forceinline__ float rcp_approx(float x) {
    float r; asm("rcp.approx.f32 %0, %1;" : "=f"(r) : "f"(x)); return r;
}
__device__ __forceinline__ float ex2_approx(float x) {
    float r; asm("ex2.approx.f32 %0, %1;" : "=f"(r) : "f"(x)); return r;
}
__device__ __forceinline__ float lg2_approx(float x) {
    float r; asm("lg2.approx.f32 %0, %1;" : "=f"(r) : "f"(x)); return r;
}

// tbl[p*3+t] = { 1.5*P[p][t],  0.1*(p!=t),  class_w[t]*ln2,  0 }
__device__ __forceinline__ void row_loss(float l0, float l1, float l2, int t,
                                         const float4* __restrict__ tbl,
                                         float& acc, float& accP)
{
    // exact first-occurrence argmax (strict > matches jnp.argmax)
    const bool  pa  = (l1 > l0);
    const float m01 = fmaxf(l0, l1);
    const bool  pb  = (l2 > m01);
    const float m   = fmaxf(m01, l2);

    const int p3  = pb ? 6 : (pa ? 3 : 0);     // p * 3
    const float4 e = tbl[p3 + t];              // {pen15, confw, aln2, -}

    // log2-domain shifted deltas; max lane is exactly 0 -> exp = 1
    const float nmK = -m * LOG2E;
    const float s0 = fmaf(l0, LOG2E, nmK);
    const float s1 = fmaf(l1, LOG2E, nmK);
    const float s2 = fmaf(l2, LOG2E, nmK);

    const float e0 = ex2_approx(s0);
    const float e1 = ex2_approx(s1);
    const float e2 = ex2_approx(s2);
    const float S    = e0 + e1 + e2;
    const float rcpS = rcp_approx(S);          // == max prob (exp at argmax is 1)
    const float lg2S = lg2_approx(S);

    // q = log2(prob[target]) = st - lg2S;  pt = 2^q;  ce2 = -q = ce/ln2
    const float st = (t == 0) ? s0 : ((t == 1) ? s1 : s2);
    const float q  = st - lg2S;
    const float pt = ex2_approx(q);            // prob[target], no et select/mul
    const float omp = 1.0f - pt;

    const float w  = e.z * omp;                // alpha*ln2 * (1-pt)
    acc  = fmaf(w * omp, -q, acc);             // focal: alpha*fw*ce  (negate q free)
    acc  = fmaf(e.y, rcpS, acc);               // 0.1*(p!=t)*max_prob
    accP += e.x;                               // 1.5*penalty
}

__global__ void __launch_bounds__(256, 6)
trading_loss_kernel(const float* __restrict__ logits,
                    const int*   __restrict__ targets,
                    const float* __restrict__ class_w,
                    float*       __restrict__ out,
                    int ngroups, float inv_n, int nblocks)
{
    __shared__ float4 tbl[9];
    __shared__ float  warp_sums[8];
    __shared__ bool   is_last;

    if (threadIdx.x < 9) {
        const int p = threadIdx.x / 3;
        const int t = threadIdx.x - p * 3;
        int d = p - t; d = (d < 0) ? -d : d;
        const float pen15 = 0.75f * (float)d + ((d == 2) ? 0.75f : 0.0f);
        const float confw = (d != 0) ? 0.1f : 0.0f;
        tbl[threadIdx.x] = make_float4(pen15, confw, class_w[t] * LN2, 0.0f);
    }
    __syncthreads();

    float acc0 = 0.0f, acc1 = 0.0f, accP = 0.0f;

    const int tid    = blockIdx.x * blockDim.x + threadIdx.x;
    const int stride = gridDim.x * blockDim.x;

    const float4* lbase = reinterpret_cast<const float4*>(logits);
    const int4*   tbase = reinterpret_cast<const int4*>(targets);

    for (int g = tid; g < ngroups; g += stride) {
        const float4 a0 = __ldg(lbase + (size_t)g * 3 + 0);
        const float4 a1 = __ldg(lbase + (size_t)g * 3 + 1);
        const float4 a2 = __ldg(lbase + (size_t)g * 3 + 2);
        const int4   t4 = __ldg(tbase + g);

        row_loss(a0.x, a0.y, a0.z, t4.x, tbl, acc0, accP);
        row_loss(a0.w, a1.x, a1.y, t4.y, tbl, acc1, accP);
        row_loss(a1.z, a1.w, a2.x, t4.z, tbl, acc0, accP);
        row_loss(a2.y, a2.z, a2.w, t4.w, tbl, acc1, accP);
    }

    float acc = (acc0 + acc1) + accP;

    // ---- block reduction ----
    #pragma unroll
    for (int off = 16; off > 0; off >>= 1)
        acc += __shfl_xor_sync(0xFFFFFFFFu, acc, off);

    const int lane = threadIdx.x & 31;
    const int wid  = threadIdx.x >> 5;
    if (lane == 0) warp_sums[wid] = acc;
    __syncthreads();

    if (wid == 0) {
        float v = (lane < (blockDim.x >> 5)) ? warp_sums[lane] : 0.0f;
        #pragma unroll
        for (int off = 4; off > 0; off >>= 1)
            v += __shfl_xor_sync(0xFFFFFFFFu, v, off);
        if (lane == 0) {
            atomicAdd(&g_acc, (double)v);
            __threadfence();
            unsigned int ticket = atomicAdd(&g_acc_count, 1u);
            is_last = (ticket == (unsigned int)nblocks - 1u);
        }
    }
    __syncthreads();

    if (is_last && threadIdx.x == 0) {
        double total = g_acc;
        out[0] = (float)(total * (double)inv_n);
        g_acc = 0.0;
        g_acc_count = 0u;
    }
}

extern "C" void kernel_launch(void* const* d_in, const int* in_sizes, int n_in,
                              void* d_out, int out_size)
{
    const float* logits  = (const float*)d_in[0];
    const int*   targets = (const int*)d_in[1];
    const float* class_w = (const float*)d_in[2];
    float*       out     = (float*)d_out;

    const int batch   = in_sizes[1];       // targets element count = B
    const int ngroups = batch / 4;         // 4 rows per float4-group

    const int threads = 256;
    int blocks = 152 * 6;                  // single resident wave (GB300: 152 SMs)
    int maxb   = (ngroups + threads - 1) / threads;
    if (blocks > maxb) blocks = maxb;
    if (blocks < 1) blocks = 1;

    trading_loss_kernel<<<blocks, threads>>>(logits, targets, class_w, out,
                                             ngroups, 1.0f / (float)batch, blocks);
}

// round 14
// speedup vs baseline: 1.2264x; 1.0507x over previous
#include <cuda_runtime.h>
#include <cuda_bf16.h>
#include <cstdint>

// Device-global scratch (no allocations). Zero-init; last block resets.
__device__ double        g_acc       = 0.0;
__device__ unsigned int  g_acc_count = 0;

#define LOG2E 1.44269504088896340736f
#define LN2   0.69314718055994530942f

__device__ __forceinline__ float rcp_approx(float x) {
    float r; asm("rcp.approx.f32 %0, %1;" : "=f"(r) : "f"(x)); return r;
}
__device__ __forceinline__ float ex2_approx(float x) {
    float r; asm("ex2.approx.f32 %0, %1;" : "=f"(r) : "f"(x)); return r;
}
__device__ __forceinline__ float lg2_approx(float x) {
    float r; asm("lg2.approx.f32 %0, %1;" : "=f"(r) : "f"(x)); return r;
}

// tbl[p*3+t] = { 1.5*P[p][t],  0.1*(p!=t),  class_w[t]*ln2,  0 }
__device__ __forceinline__ void row_loss(float l0, float l1, float l2, int t,
                                         const float4* __restrict__ tbl,
                                         float& acc, float& accP)
{
    // exact first-occurrence argmax (strict > matches jnp.argmax)
    const bool  pa  = (l1 > l0);
    const float m01 = fmaxf(l0, l1);
    const bool  pb  = (l2 > m01);
    const float m   = fmaxf(m01, l2);

    const int p3  = pb ? 6 : (pa ? 3 : 0);     // p * 3
    const float4 e = tbl[p3 + t];              // {pen15, confw, aln2, -}

    // log2-domain shifted deltas; max lane is exactly 0 -> exp = 1
    const float nmK = -m * LOG2E;
    const float s0 = fmaf(l0, LOG2E, nmK);
    const float s1 = fmaf(l1, LOG2E, nmK);
    const float s2 = fmaf(l2, LOG2E, nmK);

    const float e0 = ex2_approx(s0);
    const float e1 = ex2_approx(s1);
    const float e2 = ex2_approx(s2);
    const float S    = e0 + e1 + e2;
    const float rcpS = rcp_approx(S);          // == max prob (exp at argmax is 1)

    // pt = prob[target]; ce2 = -log2(pt) = ce/ln2   (no lg2(S), no st select)
    const float et = (t == 0) ? e0 : ((t == 1) ? e1 : e2);
    const float pt = et * rcpS;
    const float nq = lg2_approx(pt);           // log2(pt) <= 0
    const float omp = 1.0f - pt;

    const float w  = e.z * omp;                // alpha*ln2 * (1-pt)
    acc  = fmaf(w * omp, -nq, acc);            // focal: alpha*fw*ce (negation free)
    acc  = fmaf(e.y, rcpS, acc);               // 0.1*(p!=t)*max_prob
    accP += e.x;                               // 1.5*penalty
}

__global__ void __launch_bounds__(256, 6)
trading_loss_kernel(const float* __restrict__ logits,
                    const int*   __restrict__ targets,
                    const float* __restrict__ class_w,
                    float*       __restrict__ out,
                    int ngroups, float inv_n, int nblocks)
{
    __shared__ float4 tbl[9];
    __shared__ float  warp_sums[8];
    __shared__ bool   is_last;

    if (threadIdx.x < 9) {
        const int p = threadIdx.x / 3;
        const int t = threadIdx.x - p * 3;
        int d = p - t; d = (d < 0) ? -d : d;
        const float pen15 = 0.75f * (float)d + ((d == 2) ? 0.75f : 0.0f);
        const float confw = (d != 0) ? 0.1f : 0.0f;
        tbl[threadIdx.x] = make_float4(pen15, confw, class_w[t] * LN2, 0.0f);
    }
    __syncthreads();

    float acc0 = 0.0f, acc1 = 0.0f, accP = 0.0f;

    const int tid    = blockIdx.x * blockDim.x + threadIdx.x;
    const int stride = gridDim.x * blockDim.x;

    const float4* lbase = reinterpret_cast<const float4*>(logits);
    const int4*   tbase = reinterpret_cast<const int4*>(targets);

    for (int g = tid; g < ngroups; g += stride) {
        const float4 a0 = __ldg(lbase + (size_t)g * 3 + 0);
        const float4 a1 = __ldg(lbase + (size_t)g * 3 + 1);
        const float4 a2 = __ldg(lbase + (size_t)g * 3 + 2);
        const int4   t4 = __ldg(tbase + g);

        row_loss(a0.x, a0.y, a0.z, t4.x, tbl, acc0, accP);
        row_loss(a0.w, a1.x, a1.y, t4.y, tbl, acc1, accP);
        row_loss(a1.z, a1.w, a2.x, t4.z, tbl, acc0, accP);
        row_loss(a2.y, a2.z, a2.w, t4.w, tbl, acc1, accP);
    }

    float acc = (acc0 + acc1) + accP;

    // ---- block reduction ----
    #pragma unroll
    for (int off = 16; off > 0; off >>= 1)
        acc += __shfl_xor_sync(0xFFFFFFFFu, acc, off);

    const int lane = threadIdx.x & 31;
    const int wid  = threadIdx.x >> 5;
    if (lane == 0) warp_sums[wid] = acc;
    __syncthreads();

    if (wid == 0) {
        float v = (lane < (blockDim.x >> 5)) ? warp_sums[lane] : 0.0f;
        #pragma unroll
        for (int off = 4; off > 0; off >>= 1)
            v += __shfl_xor_sync(0xFFFFFFFFu, v, off);
        if (lane == 0) {
            atomicAdd(&g_acc, (double)v);
            __threadfence();
            unsigned int ticket = atomicAdd(&g_acc_count, 1u);
            is_last = (ticket == (unsigned int)nblocks - 1u);
        }
    }
    __syncthreads();

    if (is_last && threadIdx.x == 0) {
        double total = g_acc;
        out[0] = (float)(total * (double)inv_n);
        g_acc = 0.0;
        g_acc_count = 0u;
    }
}

extern "C" void kernel_launch(void* const* d_in, const int* in_sizes, int n_in,
                              void* d_out, int out_size)
{
    const float* logits  = (const float*)d_in[0];
    const int*   targets = (const int*)d_in[1];
    const float* class_w = (const float*)d_in[2];
    float*       out     = (float*)d_out;

    const int batch   = in_sizes[1];       // targets element count = B
    const int ngroups = batch / 4;         // 4 rows per float4-group

    const int threads = 256;
    int blocks = 152 * 6;                  // single resident wave (GB300: 152 SMs)
    int maxb   = (ngroups + threads - 1) / threads;
    if (blocks > maxb) blocks = maxb;
    if (blocks < 1) blocks = 1;

    trading_loss_kernel<<<blocks, threads>>>(logits, targets, class_w, out,
                                             ngroups, 1.0f / (float)batch, blocks);
}